// round 2
// baseline (speedup 1.0000x reference)
#include <cuda_runtime.h>
#include <math.h>

// Problem constants
#define BSZ   4
#define TLEN  4096
#define HD    64
#define NEMB  204
#define BQ    64
#define BK    64

#define QK_STRIDE 68   // floats per row (16B-aligned, conflict-free float4 phase reads)
#define SC_STRIDE 65   // score tile row stride

#define SCALE 0.07001400420140049f  // 1/sqrt(204)  (reference scales by embed dim!)

// Scratch for projected Q,K,V (allocation-free rule: __device__ globals)
__device__ float g_Q[BSZ * TLEN * HD];
__device__ float g_K[BSZ * TLEN * HD];
__device__ float g_V[BSZ * TLEN * HD];

// -------------------------------------------------------------------------
// Fast exp for x <= 0 — FFMA-only (avoids the MUFU pipe bottleneck: 34M exps
// at 0.5 MUFU/cyc/SM would alone cost ~230us chip-wide).
// exp(x) = 2^(x*log2e); degree-5 poly for 2^f on [0,1), err ~2e-7.
// -------------------------------------------------------------------------
__device__ __forceinline__ float fexp(float x) {
    float t = x * 1.4426950408889634f;
    t = fmaxf(t, -126.0f);                 // flush huge-negative (mask) to ~0
    float fl = floorf(t);
    float f  = t - fl;
    float p  = 1.8775767e-3f;
    p = fmaf(p, f, 8.9893397e-3f);
    p = fmaf(p, f, 5.5826318e-2f);
    p = fmaf(p, f, 2.4015361e-1f);
    p = fmaf(p, f, 6.9315308e-1f);
    p = fmaf(p, f, 1.0f);
    return __int_as_float(((int)fl + 127) << 23) * p;
}

// -------------------------------------------------------------------------
// QKV projection: one CTA = 64 rows of x. x tile in smem (warp-broadcast
// reads), W stays in L1 (156KB total, fully L1/L2 resident, reused by all
// CTAs). 4-row register blocking amortizes each W load over 12 FMAs.
// -------------------------------------------------------------------------
__global__ __launch_bounds__(256) void proj_kernel(
    const float* __restrict__ x,
    const float* __restrict__ Wq,
    const float* __restrict__ Wk,
    const float* __restrict__ Wv)
{
    __shared__ float xs[64 * NEMB];
    const int row0 = blockIdx.x * 64;
    const float* xg = x + (size_t)row0 * NEMB;

    for (int i = threadIdx.x; i < 64 * NEMB; i += 256)
        xs[i] = xg[i];
    __syncthreads();

    const int h   = threadIdx.x & 63;   // head-dim column (coalesced W reads)
    const int rhi = threadIdx.x >> 6;   // 0..3

    #pragma unroll
    for (int g = 0; g < 4; g++) {
        const int rbase = g * 16 + rhi * 4;   // 4 consecutive rows
        float aq0 = 0.f, aq1 = 0.f, aq2 = 0.f, aq3 = 0.f;
        float ak0 = 0.f, ak1 = 0.f, ak2 = 0.f, ak3 = 0.f;
        float av0 = 0.f, av1 = 0.f, av2 = 0.f, av3 = 0.f;

        const float* xr0 = &xs[(rbase + 0) * NEMB];
        const float* xr1 = &xs[(rbase + 1) * NEMB];
        const float* xr2 = &xs[(rbase + 2) * NEMB];
        const float* xr3 = &xs[(rbase + 3) * NEMB];

        #pragma unroll 4
        for (int e = 0; e < NEMB; e++) {
            const float wq = __ldg(&Wq[e * HD + h]);
            const float wk = __ldg(&Wk[e * HD + h]);
            const float wv = __ldg(&Wv[e * HD + h]);
            const float x0 = xr0[e], x1 = xr1[e], x2 = xr2[e], x3 = xr3[e];
            aq0 = fmaf(x0, wq, aq0); aq1 = fmaf(x1, wq, aq1);
            aq2 = fmaf(x2, wq, aq2); aq3 = fmaf(x3, wq, aq3);
            ak0 = fmaf(x0, wk, ak0); ak1 = fmaf(x1, wk, ak1);
            ak2 = fmaf(x2, wk, ak2); ak3 = fmaf(x3, wk, ak3);
            av0 = fmaf(x0, wv, av0); av1 = fmaf(x1, wv, av1);
            av2 = fmaf(x2, wv, av2); av3 = fmaf(x3, wv, av3);
        }

        const size_t o = (size_t)(row0 + rbase) * HD + h;
        g_Q[o + 0*HD] = aq0; g_Q[o + 1*HD] = aq1; g_Q[o + 2*HD] = aq2; g_Q[o + 3*HD] = aq3;
        g_K[o + 0*HD] = ak0; g_K[o + 1*HD] = ak1; g_K[o + 2*HD] = ak2; g_K[o + 3*HD] = ak3;
        g_V[o + 0*HD] = av0; g_V[o + 1*HD] = av1; g_V[o + 2*HD] = av2; g_V[o + 3*HD] = av3;
    }
}

// -------------------------------------------------------------------------
// Flash-attention: CTA = 64 queries of one batch, loops over 64-key tiles
// up to (and including) the diagonal block. 256 threads as 16x16 grid,
// each thread owns a 4x4 micro-tile of S (phase A) and of O (phase C).
// Q/K stored d-major (stride 68) for conflict-free float4 inner loads.
// Online softmax state (m,l) lives in registers of threads 0..63.
// -------------------------------------------------------------------------
__global__ __launch_bounds__(256) void attn_kernel(float* __restrict__ out)
{
    extern __shared__ float sm[];
    float* Qs      = sm;                        // [64][QK_STRIDE], Qs[d*68 + r]
    float* Ks      = Qs + 64 * QK_STRIDE;       // Ks[d*68 + c]
    float* Vs      = Ks + 64 * QK_STRIDE;       // Vs[k*68 + d]
    float* Ss      = Vs + 64 * QK_STRIDE;       // Ss[r*65 + c]
    float* alpha_s = Ss + 64 * SC_STRIDE;       // [64]
    float* linv_s  = alpha_s + 64;              // [64]

    const int b   = blockIdx.y;
    const int q0  = blockIdx.x * BQ;
    const int tid = threadIdx.x;
    const int tx  = tid & 15;      // key-col / dim group
    const int ty  = tid >> 4;      // query-row group

    // Load Q tile transposed: Qs[d][r]
    const float* Qg = g_Q + ((size_t)b * TLEN + q0) * HD;
    for (int i = tid; i < 64 * 64; i += 256) {
        const int r = i >> 6, d = i & 63;
        Qs[d * QK_STRIDE + r] = Qg[i];          // i == r*64 + d
    }

    float acc[4][4];
    #pragma unroll
    for (int i = 0; i < 4; i++)
        #pragma unroll
        for (int j = 0; j < 4; j++) acc[i][j] = 0.f;

    float m_i = -1e30f, l_i = 0.f;   // meaningful for tid < 64 (row = tid)

    for (int k0 = 0; k0 <= q0; k0 += BK) {
        __syncthreads();   // previous iteration's Ss/Ks/Vs reads are done

        // Load K (transposed) and V tiles
        const float* Kg = g_K + ((size_t)b * TLEN + k0) * HD;
        const float* Vg = g_V + ((size_t)b * TLEN + k0) * HD;
        for (int i = tid; i < 64 * 64; i += 256) {
            const int c = i >> 6, d = i & 63;
            Ks[d * QK_STRIDE + c] = Kg[i];
            Vs[c * QK_STRIDE + d] = Vg[i];
        }
        __syncthreads();

        // ---- Phase A: S = Q @ K^T * scale (4x4 per thread) ----
        float s[4][4];
        #pragma unroll
        for (int i = 0; i < 4; i++)
            #pragma unroll
            for (int j = 0; j < 4; j++) s[i][j] = 0.f;

        #pragma unroll 8
        for (int d = 0; d < 64; d++) {
            const float4 qv = *(const float4*)&Qs[d * QK_STRIDE + ty * 4];
            const float4 kv = *(const float4*)&Ks[d * QK_STRIDE + tx * 4];
            const float q[4] = {qv.x, qv.y, qv.z, qv.w};
            const float k[4] = {kv.x, kv.y, kv.z, kv.w};
            #pragma unroll
            for (int i = 0; i < 4; i++)
                #pragma unroll
                for (int j = 0; j < 4; j++)
                    s[i][j] = fmaf(q[i], k[j], s[i][j]);
        }

        const bool diag = (k0 == q0);
        #pragma unroll
        for (int i = 0; i < 4; i++) {
            const int r = ty * 4 + i;
            #pragma unroll
            for (int j = 0; j < 4; j++) {
                const int c = tx * 4 + j;
                float v = s[i][j] * SCALE;
                if (diag && c > r) v = -1e30f;   // causal mask
                Ss[r * SC_STRIDE + c] = v;
            }
        }
        __syncthreads();

        // ---- Phase B: online softmax, one thread per row ----
        if (tid < 64) {
            float* row = &Ss[tid * SC_STRIDE];
            float tm = -1e30f;
            #pragma unroll 8
            for (int c = 0; c < 64; c++) tm = fmaxf(tm, row[c]);
            const float mnew = fmaxf(m_i, tm);
            const float al   = fexp(m_i - mnew);
            float sum = 0.f;
            #pragma unroll 8
            for (int c = 0; c < 64; c++) {
                const float p = fexp(row[c] - mnew);
                row[c] = p;
                sum += p;
            }
            l_i = l_i * al + sum;
            m_i = mnew;
            alpha_s[tid] = al;
        }
        __syncthreads();

        // ---- Phase C: O = O*alpha + P @ V (4x4 per thread) ----
        float a[4];
        #pragma unroll
        for (int i = 0; i < 4; i++) a[i] = alpha_s[ty * 4 + i];
        #pragma unroll
        for (int i = 0; i < 4; i++)
            #pragma unroll
            for (int j = 0; j < 4; j++) acc[i][j] *= a[i];

        #pragma unroll 8
        for (int k = 0; k < 64; k++) {
            float p[4];
            #pragma unroll
            for (int i = 0; i < 4; i++)
                p[i] = Ss[(ty * 4 + i) * SC_STRIDE + k];   // warp-broadcast
            const float4 vv = *(const float4*)&Vs[k * QK_STRIDE + tx * 4];
            const float v[4] = {vv.x, vv.y, vv.z, vv.w};
            #pragma unroll
            for (int i = 0; i < 4; i++)
                #pragma unroll
                for (int j = 0; j < 4; j++)
                    acc[i][j] = fmaf(p[i], v[j], acc[i][j]);
        }
    }

    // ---- Epilogue: normalize by l, write out ----
    if (tid < 64) linv_s[tid] = 1.0f / l_i;
    __syncthreads();

    #pragma unroll
    for (int i = 0; i < 4; i++) {
        const int r = ty * 4 + i;
        const float li = linv_s[r];
        #pragma unroll
        for (int j = 0; j < 4; j++) {
            const int c = tx * 4 + j;
            out[((size_t)b * TLEN + q0 + r) * HD + c] = acc[i][j] * li;
        }
    }
}

// -------------------------------------------------------------------------
// kernel_launch: projections, then flash attention.
// -------------------------------------------------------------------------
extern "C" void kernel_launch(void* const* d_in, const int* in_sizes, int n_in,
                              void* d_out, int out_size)
{
    const float* x  = (const float*)d_in[0];
    const float* Wq = (const float*)d_in[1];
    const float* Wk = (const float*)d_in[2];
    const float* Wv = (const float*)d_in[3];
    float* out = (float*)d_out;

    // 256 CTAs x 64 rows cover B*T = 16384 rows
    proj_kernel<<<(BSZ * TLEN) / 64, 256>>>(x, Wq, Wk, Wv);

    const int smem_bytes = (3 * 64 * QK_STRIDE + 64 * SC_STRIDE + 128) * sizeof(float);
    cudaFuncSetAttribute(attn_kernel,
                         cudaFuncAttributeMaxDynamicSharedMemorySize, smem_bytes);
    attn_kernel<<<dim3(TLEN / BQ, BSZ), 256, smem_bytes>>>(out);
}

// round 4
// speedup vs baseline: 1.3274x; 1.3274x over previous
#include <cuda_runtime.h>
#include <math.h>

// Problem constants
#define BSZ   4
#define TLEN  4096
#define HD    64
#define NEMB  204
#define BQ    64
#define BK    64

#define QK_STRIDE 68   // floats per row: 16B-aligned vector access, bank-spread

#define SCALE 0.07001400420140049f  // 1/sqrt(204)  (reference scales by embed dim!)

// Scratch for projected Q,K,V (allocation-free rule: __device__ globals)
__device__ float g_Q[BSZ * TLEN * HD];
__device__ float g_K[BSZ * TLEN * HD];
__device__ float g_V[BSZ * TLEN * HD];

typedef unsigned long long u64t;

// ---- f32x2 packed helpers (Blackwell 2x fp32 path; only reachable via PTX) ----
__device__ __forceinline__ u64t pk2(float a, float b) {
    u64t r; asm("mov.b64 %0, {%1,%2};" : "=l"(r) : "f"(a), "f"(b)); return r;
}
__device__ __forceinline__ void unpk2(float& a, float& b, u64t v) {
    asm("mov.b64 {%0,%1}, %2;" : "=f"(a), "=f"(b) : "l"(v));
}
__device__ __forceinline__ u64t fma2(u64t a, u64t b, u64t c) {
    u64t d; asm("fma.rn.f32x2 %0, %1, %2, %3;" : "=l"(d) : "l"(a), "l"(b), "l"(c)); return d;
}
__device__ __forceinline__ u64t mul2(u64t a, u64t b) {
    u64t d; asm("mul.rn.f32x2 %0, %1, %2;" : "=l"(d) : "l"(a), "l"(b)); return d;
}

// -------------------------------------------------------------------------
// FFMA-only exp (avoids MUFU pipe; ~2e-7 rel err). Valid for any x<=~0.
// -------------------------------------------------------------------------
__device__ __forceinline__ float fexp(float x) {
    float t = x * 1.4426950408889634f;
    t = fmaxf(t, -126.0f);
    float fl = floorf(t);
    float f  = t - fl;
    float p  = 1.8775767e-3f;
    p = fmaf(p, f, 8.9893397e-3f);
    p = fmaf(p, f, 5.5826318e-2f);
    p = fmaf(p, f, 2.4015361e-1f);
    p = fmaf(p, f, 6.9315308e-1f);
    p = fmaf(p, f, 1.0f);
    return __int_as_float(((int)fl + 127) << 23) * p;
}

// -------------------------------------------------------------------------
// QKV projection (unchanged from R2: ~39us, not the bottleneck yet)
// -------------------------------------------------------------------------
__global__ __launch_bounds__(256) void proj_kernel(
    const float* __restrict__ x,
    const float* __restrict__ Wq,
    const float* __restrict__ Wk,
    const float* __restrict__ Wv)
{
    __shared__ float xs[64 * NEMB];
    const int row0 = blockIdx.x * 64;
    const float* xg = x + (size_t)row0 * NEMB;

    for (int i = threadIdx.x; i < 64 * NEMB; i += 256)
        xs[i] = xg[i];
    __syncthreads();

    const int h   = threadIdx.x & 63;
    const int rhi = threadIdx.x >> 6;

    #pragma unroll
    for (int g = 0; g < 4; g++) {
        const int rbase = g * 16 + rhi * 4;
        float aq0 = 0.f, aq1 = 0.f, aq2 = 0.f, aq3 = 0.f;
        float ak0 = 0.f, ak1 = 0.f, ak2 = 0.f, ak3 = 0.f;
        float av0 = 0.f, av1 = 0.f, av2 = 0.f, av3 = 0.f;

        const float* xr0 = &xs[(rbase + 0) * NEMB];
        const float* xr1 = &xs[(rbase + 1) * NEMB];
        const float* xr2 = &xs[(rbase + 2) * NEMB];
        const float* xr3 = &xs[(rbase + 3) * NEMB];

        #pragma unroll 4
        for (int e = 0; e < NEMB; e++) {
            const float wq = __ldg(&Wq[e * HD + h]);
            const float wk = __ldg(&Wk[e * HD + h]);
            const float wv = __ldg(&Wv[e * HD + h]);
            const float x0 = xr0[e], x1 = xr1[e], x2 = xr2[e], x3 = xr3[e];
            aq0 = fmaf(x0, wq, aq0); aq1 = fmaf(x1, wq, aq1);
            aq2 = fmaf(x2, wq, aq2); aq3 = fmaf(x3, wq, aq3);
            ak0 = fmaf(x0, wk, ak0); ak1 = fmaf(x1, wk, ak1);
            ak2 = fmaf(x2, wk, ak2); ak3 = fmaf(x3, wk, ak3);
            av0 = fmaf(x0, wv, av0); av1 = fmaf(x1, wv, av1);
            av2 = fmaf(x2, wv, av2); av3 = fmaf(x3, wv, av3);
        }

        const size_t o = (size_t)(row0 + rbase) * HD + h;
        g_Q[o + 0*HD] = aq0; g_Q[o + 1*HD] = aq1; g_Q[o + 2*HD] = aq2; g_Q[o + 3*HD] = aq3;
        g_K[o + 0*HD] = ak0; g_K[o + 1*HD] = ak1; g_K[o + 2*HD] = ak2; g_K[o + 3*HD] = ak3;
        g_V[o + 0*HD] = av0; g_V[o + 1*HD] = av1; g_V[o + 2*HD] = av2; g_V[o + 3*HD] = av3;
    }
}

// -------------------------------------------------------------------------
// Flash attention core for one (batch, q-tile). 256 threads as 16x16 grid:
// thread (tx,ty) owns rows ty*4..+3 and cols tx*4..+3, column-PAIR packed
// into f32x2 accumulators. Softmax fully in registers via shfl across the
// 16 lanes that own each row.
// -------------------------------------------------------------------------
__device__ void do_qtile(int b, int qt, float* __restrict__ out,
                         float* Qs, float* Ks, float* Vs, float* Ss,
                         int tid, int tx, int ty)
{
    const int q0  = qt * BQ;
    const int tx4 = tx * 4;
    const int ty4 = ty * 4;

    // Load Q tile transposed: Qs[d][r]
    __syncthreads();   // guard vs previous q-tile smem use
    const float* Qg = g_Q + ((size_t)b * TLEN + q0) * HD;
    for (int i = tid; i < 64 * 64; i += 256) {
        const int r = i >> 6, d = i & 63;
        Qs[d * QK_STRIDE + r] = Qg[i];
    }

    u64t acc[4][2];
    #pragma unroll
    for (int i = 0; i < 4; i++) { acc[i][0] = 0ull; acc[i][1] = 0ull; }
    float m_i[4], l_i[4];
    #pragma unroll
    for (int i = 0; i < 4; i++) { m_i[i] = -1e30f; l_i[i] = 0.f; }

    for (int kt = 0; kt <= qt; kt++) {
        __syncthreads();

        // Load K (transposed) and V tiles into smem
        const float* Kg = g_K + ((size_t)b * TLEN + kt * BK) * HD;
        const float* Vg = g_V + ((size_t)b * TLEN + kt * BK) * HD;
        for (int i = tid; i < 64 * 64; i += 256) {
            const int c = i >> 6, d = i & 63;
            Ks[d * QK_STRIDE + c] = Kg[i];
            Vs[c * QK_STRIDE + d] = Vg[i];
        }
        __syncthreads();

        // ---- Phase A: S = Q @ K^T (f32x2 packed over column pairs) ----
        u64t s[4][2];
        #pragma unroll
        for (int i = 0; i < 4; i++) { s[i][0] = 0ull; s[i][1] = 0ull; }

        #pragma unroll 4
        for (int d = 0; d < 64; d++) {
            const float4 qv = *(const float4*)&Qs[d * QK_STRIDE + ty4];
            const ulonglong2 kv = *(const ulonglong2*)&Ks[d * QK_STRIDE + tx4];
            const u64t q0p = pk2(qv.x, qv.x);
            const u64t q1p = pk2(qv.y, qv.y);
            const u64t q2p = pk2(qv.z, qv.z);
            const u64t q3p = pk2(qv.w, qv.w);
            s[0][0] = fma2(q0p, kv.x, s[0][0]); s[0][1] = fma2(q0p, kv.y, s[0][1]);
            s[1][0] = fma2(q1p, kv.x, s[1][0]); s[1][1] = fma2(q1p, kv.y, s[1][1]);
            s[2][0] = fma2(q2p, kv.x, s[2][0]); s[2][1] = fma2(q2p, kv.y, s[2][1]);
            s[3][0] = fma2(q3p, kv.x, s[3][0]); s[3][1] = fma2(q3p, kv.y, s[3][1]);
        }

        // Unpack, scale, mask
        float sf[4][4];
        const bool diag = (kt == qt);
        #pragma unroll
        for (int i = 0; i < 4; i++) {
            unpk2(sf[i][0], sf[i][1], s[i][0]);
            unpk2(sf[i][2], sf[i][3], s[i][1]);
            #pragma unroll
            for (int j = 0; j < 4; j++) {
                sf[i][j] *= SCALE;
                if (diag && (tx4 + j) > (ty4 + i)) sf[i][j] = -1e30f;
            }
        }

        // ---- In-register online softmax (row spread over 16 lanes) ----
        float al[4];
        #pragma unroll
        for (int i = 0; i < 4; i++) {
            float rm = fmaxf(fmaxf(sf[i][0], sf[i][1]), fmaxf(sf[i][2], sf[i][3]));
            rm = fmaxf(rm, __shfl_xor_sync(0xffffffffu, rm, 1));
            rm = fmaxf(rm, __shfl_xor_sync(0xffffffffu, rm, 2));
            rm = fmaxf(rm, __shfl_xor_sync(0xffffffffu, rm, 4));
            rm = fmaxf(rm, __shfl_xor_sync(0xffffffffu, rm, 8));
            const float mnew = fmaxf(m_i[i], rm);
            al[i] = fexp(m_i[i] - mnew);
            m_i[i] = mnew;
            float p0 = fexp(sf[i][0] - mnew);
            float p1 = fexp(sf[i][1] - mnew);
            float p2 = fexp(sf[i][2] - mnew);
            float p3 = fexp(sf[i][3] - mnew);
            sf[i][0] = p0; sf[i][1] = p1; sf[i][2] = p2; sf[i][3] = p3;
            float rs = (p0 + p1) + (p2 + p3);
            rs += __shfl_xor_sync(0xffffffffu, rs, 1);
            rs += __shfl_xor_sync(0xffffffffu, rs, 2);
            rs += __shfl_xor_sync(0xffffffffu, rs, 4);
            rs += __shfl_xor_sync(0xffffffffu, rs, 8);
            l_i[i] = l_i[i] * al[i] + rs;
            // store P row chunk for phase C
            *(float4*)&Ss[(ty4 + i) * QK_STRIDE + tx4] = make_float4(p0, p1, p2, p3);
        }

        // rescale accumulators
        #pragma unroll
        for (int i = 0; i < 4; i++) {
            const u64t ap = pk2(al[i], al[i]);
            acc[i][0] = mul2(acc[i][0], ap);
            acc[i][1] = mul2(acc[i][1], ap);
        }
        __syncthreads();

        // ---- Phase C: O += P @ V (f32x2 packed over dim pairs) ----
        #pragma unroll 2
        for (int k0 = 0; k0 < 64; k0 += 4) {
            float4 pr[4];
            #pragma unroll
            for (int i = 0; i < 4; i++)
                pr[i] = *(const float4*)&Ss[(ty4 + i) * QK_STRIDE + k0];
            #pragma unroll
            for (int kk = 0; kk < 4; kk++) {
                const ulonglong2 vv = *(const ulonglong2*)&Vs[(k0 + kk) * QK_STRIDE + tx4];
                const float pk[4] = { ((const float*)&pr[0])[kk], ((const float*)&pr[1])[kk],
                                      ((const float*)&pr[2])[kk], ((const float*)&pr[3])[kk] };
                #pragma unroll
                for (int i = 0; i < 4; i++) {
                    const u64t pp = pk2(pk[i], pk[i]);
                    acc[i][0] = fma2(pp, vv.x, acc[i][0]);
                    acc[i][1] = fma2(pp, vv.y, acc[i][1]);
                }
            }
        }
    }

    // ---- Epilogue: normalize and write ----
    #pragma unroll
    for (int i = 0; i < 4; i++) {
        const float linv = 1.0f / l_i[i];
        float o0, o1, o2, o3;
        unpk2(o0, o1, acc[i][0]);
        unpk2(o2, o3, acc[i][1]);
        const int r = q0 + ty4 + i;
        *(float4*)&out[((size_t)b * TLEN + r) * HD + tx4] =
            make_float4(o0 * linv, o1 * linv, o2 * linv, o3 * linv);
    }
}

// -------------------------------------------------------------------------
// Balanced scheduler: CTA (bx, b) handles q-tiles bx and 63-bx of batch b.
// Work = (bx+1) + (64-bx) = 65 k-tiles for EVERY CTA. 128 CTAs = 1 wave.
// -------------------------------------------------------------------------
__global__ __launch_bounds__(256) void attn_kernel(float* __restrict__ out)
{
    extern __shared__ float sm[];
    float* Qs = sm;
    float* Ks = Qs + 64 * QK_STRIDE;
    float* Vs = Ks + 64 * QK_STRIDE;
    float* Ss = Vs + 64 * QK_STRIDE;

    const int b   = blockIdx.y;
    const int tid = threadIdx.x;
    const int tx  = tid & 15;
    const int ty  = tid >> 4;

    do_qtile(b, blockIdx.x,      out, Qs, Ks, Vs, Ss, tid, tx, ty);
    do_qtile(b, 63 - blockIdx.x, out, Qs, Ks, Vs, Ss, tid, tx, ty);
}

extern "C" void kernel_launch(void* const* d_in, const int* in_sizes, int n_in,
                              void* d_out, int out_size)
{
    const float* x  = (const float*)d_in[0];
    const float* Wq = (const float*)d_in[1];
    const float* Wk = (const float*)d_in[2];
    const float* Wv = (const float*)d_in[3];
    float* out = (float*)d_out;

    proj_kernel<<<(BSZ * TLEN) / 64, 256>>>(x, Wq, Wk, Wv);

    const int smem_bytes = 4 * 64 * QK_STRIDE * sizeof(float);
    cudaFuncSetAttribute(attn_kernel,
                         cudaFuncAttributeMaxDynamicSharedMemorySize, smem_bytes);
    attn_kernel<<<dim3(32, BSZ), 256, smem_bytes>>>(out);
}